// round 16
// baseline (speedup 1.0000x reference)
#include <cuda_runtime.h>
#include <cuda_fp16.h>
#include <cstdint>

// ---------------------------------------------------------------------------
// Scratch (device globals — no allocation allowed)
// ---------------------------------------------------------------------------
__device__ __half g_xhi[8388608];    // x fp16 [8192,1024]
__device__ __half g_wthi[4194304];   // Wq^T*qscale (1M) | Wkv^T (2M) | Wo^T (1M)
__device__ __half g_qkv[25165824];   // fused [8192, 3072] : q | k | v
__device__ __half g_ohi[8388608];    // attn out fp16 [8192,1024]

// ---------------------------------------------------------------------------
// PTX helpers (baseline sm_80+: HMMA / ldmatrix / cp.async)
// ---------------------------------------------------------------------------
__device__ __forceinline__ uint32_t smem_u32(const void* p) {
    uint32_t a;
    asm("{ .reg .u64 t; cvta.to.shared.u64 t, %1; cvt.u32.u64 %0, t; }" : "=r"(a) : "l"(p));
    return a;
}
#define CP_ASYNC16(dst, src) \
    asm volatile("cp.async.cg.shared.global [%0], [%1], 16;" :: "r"(dst), "l"(src) : "memory")
#define CP_COMMIT()  asm volatile("cp.async.commit_group;" ::: "memory")
#define CP_WAIT1()   asm volatile("cp.async.wait_group 1;" ::: "memory")
#define CP_WAIT0()   asm volatile("cp.async.wait_group 0;" ::: "memory")

__device__ __forceinline__ void ldsm4(uint32_t* r, uint32_t addr) {
    asm volatile("ldmatrix.sync.aligned.m8n8.x4.shared.b16 {%0,%1,%2,%3}, [%4];"
                 : "=r"(r[0]), "=r"(r[1]), "=r"(r[2]), "=r"(r[3]) : "r"(addr));
}
__device__ __forceinline__ void ldsm4t(uint32_t* r, uint32_t addr) {
    asm volatile("ldmatrix.sync.aligned.m8n8.x4.trans.shared.b16 {%0,%1,%2,%3}, [%4];"
                 : "=r"(r[0]), "=r"(r[1]), "=r"(r[2]), "=r"(r[3]) : "r"(addr));
}
__device__ __forceinline__ void mma16816(float* c, const uint32_t* a, uint32_t b0, uint32_t b1) {
    asm volatile(
        "mma.sync.aligned.m16n8k16.row.col.f32.f16.f16.f32 "
        "{%0,%1,%2,%3}, {%4,%5,%6,%7}, {%8,%9}, {%0,%1,%2,%3};"
        : "+f"(c[0]), "+f"(c[1]), "+f"(c[2]), "+f"(c[3])
        : "r"(a[0]), "r"(a[1]), "r"(a[2]), "r"(a[3]), "r"(b0), "r"(b1));
}
__device__ __forceinline__ uint32_t pf16(float x, float y) {
    __half2 p = __floats2half2_rn(x, y);
    return *(uint32_t*)&p;
}

// ---------------------------------------------------------------------------
// Packed f32x2 helpers (Blackwell: add/sub/fma/mul.rn.f32x2)
// ---------------------------------------------------------------------------
typedef unsigned long long u64;
__device__ __forceinline__ u64 pk64(float x, float y) {
    u64 r; asm("mov.b64 %0, {%1, %2};" : "=l"(r) : "f"(x), "f"(y)); return r;
}
__device__ __forceinline__ u64 dup2(float c) {
    u64 r; asm("mov.b64 %0, {%1, %1};" : "=l"(r) : "f"(c)); return r;
}
__device__ __forceinline__ void upk64(u64 v, float& x, float& y) {
    asm("mov.b64 {%0, %1}, %2;" : "=f"(x), "=f"(y) : "l"(v));
}
__device__ __forceinline__ u64 addx2(u64 a, u64 b) {
    u64 r; asm("add.rn.f32x2 %0, %1, %2;" : "=l"(r) : "l"(a), "l"(b)); return r;
}
__device__ __forceinline__ u64 subx2(u64 a, u64 b) {
    u64 r; asm("sub.rn.f32x2 %0, %1, %2;" : "=l"(r) : "l"(a), "l"(b)); return r;
}
__device__ __forceinline__ u64 fmx2(u64 a, u64 b, u64 c) {
    u64 r; asm("fma.rn.f32x2 %0, %1, %2, %3;" : "=l"(r) : "l"(a), "l"(b), "l"(c)); return r;
}
__device__ __forceinline__ u64 mulx2(u64 a, u64 b) {
    u64 r; asm("mul.rn.f32x2 %0, %1, %2;" : "=l"(r) : "l"(a), "l"(b)); return r;
}

// Packed exp2 for two scores in [-30, +30] (NO clamp; masked scores use -30).
__device__ __forceinline__ u64 exp2x2(u64 xy) {
    const u64 MAGIC = 0x4B4000004B400000ULL;       // 12582912 in both lanes
    u64 xr = addx2(xy, MAGIC);
    u64 fl = subx2(xr, MAGIC);
    u64 f  = subx2(xy, fl);                        // f in [-0.5, 0.5]
    u64 p  = fmx2(dup2(9.6181291e-3f), f, dup2(5.5504109e-2f));
    p = fmx2(p, f, dup2(2.4022651e-1f));
    p = fmx2(p, f, dup2(6.9314718e-1f));
    p = fmx2(p, f, dup2(1.0f));
    uint32_t xl, xh;
    asm("mov.b64 {%0, %1}, %2;" : "=r"(xl), "=r"(xh) : "l"(xr));
    uint32_t sl = (xl - 0x4B3FFF81u) << 23;        // bits of 2^round(x)
    uint32_t sh = (xh - 0x4B3FFF81u) << 23;
    u64 sc;
    asm("mov.b64 %0, {%1, %2};" : "=l"(sc) : "r"(sl), "r"(sh));
    return mulx2(p, sc);
}

// ---------------------------------------------------------------------------
// Fused prep: z=0 Wq^T*qscale, z=1 Wkv^T, z=2 Wo^T, z=3 cast x -> fp16
// grid (64, 32, 4), block (32, 8)
// ---------------------------------------------------------------------------
__global__ void __launch_bounds__(256) conv_all(const float* __restrict__ x,
                                                __half* __restrict__ xhi,
                                                const float* __restrict__ W0,
                                                const float* __restrict__ W1,
                                                const float* __restrict__ W2,
                                                __half* __restrict__ T,
                                                float qscale)
{
    const int z  = blockIdx.z;
    const int tx = threadIdx.x, ty = threadIdx.y;

    if (z == 3) {   // cast x
        size_t idx = ((size_t)blockIdx.y * 64 + blockIdx.x) * 256 + ty * 32 + tx;
        const float4* in4 = (const float4*)x;
        uint2* out4 = (uint2*)xhi;
#pragma unroll
        for (int j = 0; j < 4; j++) {
            size_t i4 = idx * 4 + j;
            float4 v = in4[i4];
            __half2 hp0 = __floats2half2_rn(v.x, v.y);
            __half2 hp1 = __floats2half2_rn(v.z, v.w);
            uint2 hv;
            hv.x = *(uint32_t*)&hp0; hv.y = *(uint32_t*)&hp1;
            out4[i4] = hv;
        }
        return;
    }

    const float* W; __half* Thi; int N; float scale = 1.0f;
    if (z == 0)      { if (blockIdx.x >= 32) return; W = W0; Thi = T;           N = 1024; scale = qscale; }
    else if (z == 1) {                               W = W1; Thi = T + 1048576; N = 2048; }
    else             { if (blockIdx.x >= 32) return; W = W2; Thi = T + 3145728; N = 1024; }

    __shared__ float s[32][33];
    const int kt = blockIdx.y * 32, nt = blockIdx.x * 32;
#pragma unroll
    for (int r = 0; r < 4; r++) {
        int k = ty + r * 8;
        s[k][tx] = W[(size_t)(kt + k) * N + nt + tx];
    }
    __syncthreads();
#pragma unroll
    for (int r = 0; r < 4; r++) {
        int n = ty + r * 8;
        Thi[(size_t)(nt + n) * 1024 + kt + tx] = __float2half_rn(s[tx][n] * scale);
    }
}

// ---------------------------------------------------------------------------
// HMMA fp16 GEMM (1-term):  C = Ahi @ Bhi^T   (B pre-transposed [N][K=1024])
// Tile 128x128, K-chunk 64, 256 thr, warp tile 32x64, double-buffered cp.async.
// Output: fp32 (+bias) if C, else fp16.
// ---------------------------------------------------------------------------
#define TILE_B    18432          // 128 rows * 144 B
#define GEMM_SMEM (2 * 2 * TILE_B)   // 73728

__global__ void __launch_bounds__(256) gemm_hmma(const __half* __restrict__ Ahi,
                                                 const __half* __restrict__ Bhi,
                                                 float* __restrict__ C,
                                                 __half* __restrict__ Chi,
                                                 int N,
                                                 const float* __restrict__ bias)
{
    extern __shared__ char smem[];
    const uint32_t sbase = smem_u32(smem);
    const int t    = threadIdx.x;
    const int lane = t & 31;
    const int wid  = t >> 5;
    const int bm   = blockIdx.y * 128;
    const int bn   = blockIdx.x * 128;
    const int wm   = (wid >> 1) * 32;
    const int wn   = (wid & 1) * 64;

    const uint32_t a_off = (uint32_t)(wm + (lane & 15)) * 144 + (uint32_t)(lane >> 4) * 16;
    const uint32_t b_off = (uint32_t)(wn + ((lane >> 4) & 1) * 8 + (lane & 7)) * 144
                         + (uint32_t)((lane >> 3) & 1) * 16;

    const __half* srcs[2] = { Ahi + (size_t)bm * 1024, Bhi + (size_t)bn * 1024 };

    auto issue = [&](int it) {
        const uint32_t bufb = sbase + (it & 1) * (2 * TILE_B);
        const int k0 = it * 64;
#pragma unroll
        for (int r = 0; r < 2; r++) {
            const __half* gb = srcs[r] + k0;
            const uint32_t sb = bufb + r * TILE_B;
#pragma unroll
            for (int i = 0; i < 4; i++) {
                int c   = i * 256 + t;
                int row = c >> 3;
                int col = c & 7;
                CP_ASYNC16(sb + row * 144 + col * 16,
                           gb + (size_t)row * 1024 + col * 8);
            }
        }
        CP_COMMIT();
    };

    float c[2][8][4];
#pragma unroll
    for (int mi = 0; mi < 2; mi++)
#pragma unroll
        for (int nj = 0; nj < 8; nj++)
#pragma unroll
            for (int k = 0; k < 4; k++) c[mi][nj][k] = 0.f;

    issue(0);
    issue(1);

    const int NITER = 16;
    for (int it = 0; it < NITER; it++) {
        if (it + 1 < NITER) { CP_WAIT1(); } else { CP_WAIT0(); }
        __syncthreads();

        const uint32_t bufb = sbase + (it & 1) * (2 * TILE_B);
        const uint32_t Ah = bufb, Bh = bufb + TILE_B;

#pragma unroll
        for (int ks = 0; ks < 4; ks++) {
            const uint32_t ko = ks * 32;
            uint32_t ah0[4], ah1[4];
            ldsm4(ah0, Ah + a_off + ko);
            ldsm4(ah1, Ah + a_off + 16 * 144 + ko);
            uint32_t bh[4][4];
#pragma unroll
            for (int jj = 0; jj < 4; jj++)
                ldsm4(bh[jj], Bh + b_off + jj * 16 * 144 + ko);
#pragma unroll
            for (int nj = 0; nj < 8; nj++) {
                const uint32_t b0 = bh[nj >> 1][(nj & 1) * 2], b1 = bh[nj >> 1][(nj & 1) * 2 + 1];
                mma16816(c[0][nj], ah0, b0, b1);
                mma16816(c[1][nj], ah1, b0, b1);
            }
        }
        __syncthreads();
        if (it + 2 < NITER) issue(it + 2);
    }

    const int g = lane >> 2, tg = lane & 3;
#pragma unroll
    for (int mi = 0; mi < 2; mi++) {
#pragma unroll
        for (int nj = 0; nj < 8; nj++) {
            int row = bm + wm + 16 * mi + g;
            int col = bn + wn + 8 * nj + 2 * tg;
            if (Chi) {
                *(uint32_t*)(Chi + (size_t)row * N + col)       = pf16(c[mi][nj][0], c[mi][nj][1]);
                *(uint32_t*)(Chi + (size_t)(row + 8) * N + col) = pf16(c[mi][nj][2], c[mi][nj][3]);
            } else {
                float b0 = 0.f, b1 = 0.f;
                if (bias) { b0 = bias[col]; b1 = bias[col + 1]; }
                float2 v0 = make_float2(c[mi][nj][0] + b0, c[mi][nj][1] + b1);
                float2 v1 = make_float2(c[mi][nj][2] + b0, c[mi][nj][3] + b1);
                *(float2*)(C + (size_t)row * N + col)       = v0;
                *(float2*)(C + (size_t)(row + 8) * N + col) = v1;
            }
        }
    }
}

// ---------------------------------------------------------------------------
// HMMA causal flash attention, unnormalized exp2 softmax, packed-f32x2 exp.
// 128-key kv buffers (double-buffered, 2 CTAs/SM preserved: smem 73728 B),
// processed in two 64-key halves; exp interleaved with PV; 16-key-group
// masking skip (QK + mask + exp + PV only over live groups).
// ---------------------------------------------------------------------------
#define KT2_B   18432           // 128 rows * 144 B
#define ABUF_B  (2 * KT2_B)     // K | V  = 36864
#define ATTN_SMEM (2 * ABUF_B)  // 73728
#define QKV_LD 3072

__global__ void __launch_bounds__(256) attn_mma(const __half* __restrict__ QKV,
                                                __half* __restrict__ Ohi)
{
    extern __shared__ char smem[];
    const uint32_t sbase = smem_u32(smem);
    const int t    = threadIdx.x;
    const int lane = t & 31;
    const int wid  = t >> 5;
    const int g    = lane >> 2;
    const int tg   = lane & 3;

    const int qt = 15 - (int)blockIdx.x;     // heavy tiles first
    const int h  = blockIdx.y;
    const int b  = blockIdx.z;
    const int qb = qt * 128;
    const int wm = wid * 16;
    const int lastkey = qb + wm + 15;        // last unmasked key for this warp

    // -------- stage Q tile (128 x 64) into smem, load A frags --------
    {
        const __half* qh_g = QKV + ((size_t)(b * 2048 + qb)) * QKV_LD + h * 64;
#pragma unroll
        for (int i = 0; i < 4; i++) {
            int idx = i * 256 + t;           // 0..1023
            int row = idx >> 3, cc = idx & 7;
            CP_ASYNC16(sbase + row * 144 + cc * 16, qh_g + (size_t)row * QKV_LD + cc * 8);
        }
        CP_COMMIT();
        CP_WAIT0();
        __syncthreads();
    }
    uint32_t qh[4][4];
    {
        const uint32_t a_base = (uint32_t)(wm + (lane & 15)) * 144 + (uint32_t)(lane >> 4) * 16;
#pragma unroll
        for (int ks = 0; ks < 4; ks++)
            ldsm4(qh[ks], sbase + a_base + ks * 32);
    }
    __syncthreads();   // Q frags in regs before buffers get overwritten

    // -------- kv pipeline: 128-key tiles, double-buffered --------
    const __half* kv_base = QKV + ((size_t)(b * 2048)) * QKV_LD + h * 64;
    const int ntk2 = qt + 1;                 // number of 128-key tiles

    auto issue = [&](int kt2) {
        const uint32_t bufb = sbase + (kt2 & 1) * ABUF_B;
        const size_t rbase = (size_t)(kt2 * 128) * QKV_LD;
        const __half* srcs[2] = { kv_base + rbase + 1024, kv_base + rbase + 2048 }; // K | V
#pragma unroll
        for (int r = 0; r < 2; r++) {
#pragma unroll
            for (int i = 0; i < 4; i++) {
                int idx = i * 256 + t;       // 0..1023 (128 rows x 8 chunks)
                int row = idx >> 3, cc = idx & 7;
                CP_ASYNC16(bufb + r * KT2_B + row * 144 + cc * 16,
                           srcs[r] + (size_t)row * QKV_LD + cc * 8);
            }
        }
        CP_COMMIT();
    };

    issue(0);
    if (ntk2 > 1) issue(1);

    u64 lacc0 = pk64(0.f, 0.f), lacc1 = pk64(0.f, 0.f);   // packed partial row sums
    float o[8][4];
#pragma unroll
    for (int nj = 0; nj < 8; nj++)
#pragma unroll
        for (int k = 0; k < 4; k++) o[nj][k] = 0.f;

    const uint32_t b_off = (uint32_t)(((lane >> 4) & 1) * 8 + (lane & 7)) * 144
                         + (uint32_t)((lane >> 3) & 1) * 16;
    const uint32_t v_off = (uint32_t)((lane & 7) + ((lane >> 3) & 1) * 8) * 144
                         + (uint32_t)(lane >> 4) * 16;

    for (int kt2 = 0; kt2 < ntk2; kt2++) {
        if (kt2 + 1 < ntk2) { CP_WAIT1(); } else { CP_WAIT0(); }
        __syncthreads();

        const uint32_t bufb = sbase + (kt2 & 1) * ABUF_B;

#pragma unroll
        for (int hh = 0; hh < 2; hh++) {
            const int kb = kt2 * 128 + hh * 64;
            if (kb > lastkey) break;         // fully-masked half

            // live 16-key groups in this half for this warp
            const int ngrp = min(4, ((lastkey - kb) >> 4) + 1);

            const uint32_t Kh = bufb + hh * 9216;
            const uint32_t Vh = bufb + KT2_B + hh * 9216;

            // ---- S = Q K^T (live groups only) ----
            float s[8][4];
#pragma unroll
            for (int nj = 0; nj < 8; nj++)
#pragma unroll
                for (int k = 0; k < 4; k++) s[nj][k] = 0.f;

#pragma unroll
            for (int ks = 0; ks < 4; ks++) {
                const uint32_t ko = ks * 32;
#pragma unroll
                for (int nj2 = 0; nj2 < 4; nj2++) {
                    if (nj2 >= ngrp) break;
                    uint32_t kh[4];
                    ldsm4(kh, Kh + b_off + nj2 * 16 * 144 + ko);
                    mma16816(s[2 * nj2],     qh[ks], kh[0], kh[1]);
                    mma16816(s[2 * nj2 + 1], qh[ks], kh[2], kh[3]);
                }
            }

            // ---- causal mask: -30 (live groups only) ----
            const int row0 = qb + wm + g, row1 = row0 + 8;
            if (kb + 63 > qb + wm) {
#pragma unroll
                for (int nj = 0; nj < 8; nj++) {
                    if (nj >= 2 * ngrp) break;
                    int col = kb + 8 * nj + 2 * tg;
                    if (col     > row0) s[nj][0] = -30.f;
                    if (col + 1 > row0) s[nj][1] = -30.f;
                    if (col     > row1) s[nj][2] = -30.f;
                    if (col + 1 > row1) s[nj][3] = -30.f;
                }
            }

            // ---- interleaved exp + PV (live groups only) ----
#pragma unroll
            for (int ks = 0; ks < 4; ks++) {
                if (ks >= ngrp) break;
                u64 p01a = exp2x2(pk64(s[2 * ks][0],     s[2 * ks][1]));
                u64 p23a = exp2x2(pk64(s[2 * ks][2],     s[2 * ks][3]));
                u64 p01b = exp2x2(pk64(s[2 * ks + 1][0], s[2 * ks + 1][1]));
                u64 p23b = exp2x2(pk64(s[2 * ks + 1][2], s[2 * ks + 1][3]));
                lacc0 = addx2(lacc0, addx2(p01a, p01b));
                lacc1 = addx2(lacc1, addx2(p23a, p23b));
                uint32_t phi[4];
                float fa, fb;
                upk64(p01a, fa, fb); phi[0] = pf16(fa, fb);
                upk64(p23a, fa, fb); phi[1] = pf16(fa, fb);
                upk64(p01b, fa, fb); phi[2] = pf16(fa, fb);
                upk64(p23b, fa, fb); phi[3] = pf16(fa, fb);

                const uint32_t kro = ks * 16 * 144;
#pragma unroll
                for (int dc = 0; dc < 4; dc++) {
                    uint32_t vh[4];
                    ldsm4t(vh, Vh + v_off + kro + dc * 32);
                    mma16816(o[2 * dc],     phi, vh[0], vh[1]);
                    mma16816(o[2 * dc + 1], phi, vh[2], vh[3]);
                }
            }
        }

        __syncthreads();
        if (kt2 + 2 < ntk2) issue(kt2 + 2);
    }

    // ---- final row-sum reduction, epilogue ----
    float la, lb, l0, l1;
    upk64(lacc0, la, lb); l0 = la + lb;
    upk64(lacc1, la, lb); l1 = la + lb;
    l0 += __shfl_xor_sync(0xffffffffu, l0, 1);
    l0 += __shfl_xor_sync(0xffffffffu, l0, 2);
    l1 += __shfl_xor_sync(0xffffffffu, l1, 1);
    l1 += __shfl_xor_sync(0xffffffffu, l1, 2);
    const float inv0 = 1.0f / l0, inv1 = 1.0f / l1;
    const int row0 = b * 2048 + qb + wm + g;
#pragma unroll
    for (int nj = 0; nj < 8; nj++) {
        int col = h * 64 + 8 * nj + 2 * tg;
        *(uint32_t*)(Ohi + (size_t)row0 * 1024 + col)       = pf16(o[nj][0] * inv0, o[nj][1] * inv0);
        *(uint32_t*)(Ohi + (size_t)(row0 + 8) * 1024 + col) = pf16(o[nj][2] * inv1, o[nj][3] * inv1);
    }
}

// ---------------------------------------------------------------------------
// Launch
// ---------------------------------------------------------------------------
extern "C" void kernel_launch(void* const* d_in, const int* in_sizes, int n_in,
                              void* d_out, int out_size)
{
    (void)in_sizes; (void)n_in; (void)out_size;
    const float* x   = (const float*)d_in[0];
    const float* Wq  = (const float*)d_in[1];
    const float* Wkv = (const float*)d_in[2];
    const float* Wo  = (const float*)d_in[3];
    const float* bo  = (const float*)d_in[4];
    float* out = (float*)d_out;

    __half *xhi, *wthi, *qkv, *ohi;
    cudaGetSymbolAddress((void**)&xhi,  g_xhi);
    cudaGetSymbolAddress((void**)&wthi, g_wthi);
    cudaGetSymbolAddress((void**)&qkv,  g_qkv);
    cudaGetSymbolAddress((void**)&ohi,  g_ohi);

    cudaFuncSetAttribute(gemm_hmma, cudaFuncAttributeMaxDynamicSharedMemorySize, GEMM_SMEM);
    cudaFuncSetAttribute(attn_mma,  cudaFuncAttributeMaxDynamicSharedMemorySize, ATTN_SMEM);

    __half *wo_hi = wthi + 3145728;
    const float qscale = 0.125f * 1.4426950408889634f;   // D^-0.5 * log2(e)

    // fused prep: weight transposes + x cast in one launch
    conv_all<<<dim3(64, 32, 4), dim3(32, 8)>>>(x, xhi, Wq, Wkv, Wo, wthi, qscale);

    // fused qkv = x @ [Wq*qscale | Wkv]  -> fp16 [8192, 3072]
    gemm_hmma<<<dim3(24, 64), 256, GEMM_SMEM>>>(xhi, wthi, nullptr, qkv, 3072, nullptr);
    // attention -> fp16
    attn_mma<<<dim3(16, 16, 4), 256, ATTN_SMEM>>>(qkv, ohi);
    // out = o @ Wo + bo -> fp32
    gemm_hmma<<<dim3(8, 64), 256, GEMM_SMEM>>>(ohi, wo_hi, out, nullptr, 1024, bo);
}

// round 17
// speedup vs baseline: 1.0315x; 1.0315x over previous
#include <cuda_runtime.h>
#include <cuda_fp16.h>
#include <cstdint>

// ---------------------------------------------------------------------------
// Scratch (device globals — no allocation allowed)
// ---------------------------------------------------------------------------
__device__ __half g_xhi[8388608];    // x fp16 [8192,1024]
__device__ __half g_wthi[4194304];   // Wq^T*qscale (1M) | Wkv^T (2M) | Wo^T (1M)
__device__ __half g_qkv[25165824];   // fused [8192, 3072] : q | k | v
__device__ __half g_ohi[8388608];    // attn out fp16 [8192,1024]

// ---------------------------------------------------------------------------
// PTX helpers (baseline sm_80+: HMMA / ldmatrix / cp.async)
// ---------------------------------------------------------------------------
__device__ __forceinline__ uint32_t smem_u32(const void* p) {
    uint32_t a;
    asm("{ .reg .u64 t; cvta.to.shared.u64 t, %1; cvt.u32.u64 %0, t; }" : "=r"(a) : "l"(p));
    return a;
}
#define CP_ASYNC16(dst, src) \
    asm volatile("cp.async.cg.shared.global [%0], [%1], 16;" :: "r"(dst), "l"(src) : "memory")
#define CP_COMMIT()  asm volatile("cp.async.commit_group;" ::: "memory")
#define CP_WAIT1()   asm volatile("cp.async.wait_group 1;" ::: "memory")
#define CP_WAIT0()   asm volatile("cp.async.wait_group 0;" ::: "memory")

__device__ __forceinline__ void ldsm4(uint32_t* r, uint32_t addr) {
    asm volatile("ldmatrix.sync.aligned.m8n8.x4.shared.b16 {%0,%1,%2,%3}, [%4];"
                 : "=r"(r[0]), "=r"(r[1]), "=r"(r[2]), "=r"(r[3]) : "r"(addr));
}
__device__ __forceinline__ void ldsm4t(uint32_t* r, uint32_t addr) {
    asm volatile("ldmatrix.sync.aligned.m8n8.x4.trans.shared.b16 {%0,%1,%2,%3}, [%4];"
                 : "=r"(r[0]), "=r"(r[1]), "=r"(r[2]), "=r"(r[3]) : "r"(addr));
}
__device__ __forceinline__ void mma16816(float* c, const uint32_t* a, uint32_t b0, uint32_t b1) {
    asm volatile(
        "mma.sync.aligned.m16n8k16.row.col.f32.f16.f16.f32 "
        "{%0,%1,%2,%3}, {%4,%5,%6,%7}, {%8,%9}, {%0,%1,%2,%3};"
        : "+f"(c[0]), "+f"(c[1]), "+f"(c[2]), "+f"(c[3])
        : "r"(a[0]), "r"(a[1]), "r"(a[2]), "r"(a[3]), "r"(b0), "r"(b1));
}
__device__ __forceinline__ uint32_t pf16(float x, float y) {
    __half2 p = __floats2half2_rn(x, y);
    return *(uint32_t*)&p;
}

// ---------------------------------------------------------------------------
// Packed f32x2 helpers (Blackwell: add/sub/fma/mul.rn.f32x2)
// ---------------------------------------------------------------------------
typedef unsigned long long u64;
__device__ __forceinline__ u64 pk64(float x, float y) {
    u64 r; asm("mov.b64 %0, {%1, %2};" : "=l"(r) : "f"(x), "f"(y)); return r;
}
__device__ __forceinline__ u64 dup2(float c) {
    u64 r; asm("mov.b64 %0, {%1, %1};" : "=l"(r) : "f"(c)); return r;
}
__device__ __forceinline__ void upk64(u64 v, float& x, float& y) {
    asm("mov.b64 {%0, %1}, %2;" : "=f"(x), "=f"(y) : "l"(v));
}
__device__ __forceinline__ u64 addx2(u64 a, u64 b) {
    u64 r; asm("add.rn.f32x2 %0, %1, %2;" : "=l"(r) : "l"(a), "l"(b)); return r;
}
__device__ __forceinline__ u64 subx2(u64 a, u64 b) {
    u64 r; asm("sub.rn.f32x2 %0, %1, %2;" : "=l"(r) : "l"(a), "l"(b)); return r;
}
__device__ __forceinline__ u64 fmx2(u64 a, u64 b, u64 c) {
    u64 r; asm("fma.rn.f32x2 %0, %1, %2, %3;" : "=l"(r) : "l"(a), "l"(b), "l"(c)); return r;
}
__device__ __forceinline__ u64 mulx2(u64 a, u64 b) {
    u64 r; asm("mul.rn.f32x2 %0, %1, %2;" : "=l"(r) : "l"(a), "l"(b)); return r;
}

// Packed exp2 for two scores in [-30, +30] (NO clamp; masked scores use -30).
__device__ __forceinline__ u64 exp2x2(u64 xy) {
    const u64 MAGIC = 0x4B4000004B400000ULL;       // 12582912 in both lanes
    u64 xr = addx2(xy, MAGIC);
    u64 fl = subx2(xr, MAGIC);
    u64 f  = subx2(xy, fl);                        // f in [-0.5, 0.5]
    u64 p  = fmx2(dup2(9.6181291e-3f), f, dup2(5.5504109e-2f));
    p = fmx2(p, f, dup2(2.4022651e-1f));
    p = fmx2(p, f, dup2(6.9314718e-1f));
    p = fmx2(p, f, dup2(1.0f));
    uint32_t xl, xh;
    asm("mov.b64 {%0, %1}, %2;" : "=r"(xl), "=r"(xh) : "l"(xr));
    uint32_t sl = (xl - 0x4B3FFF81u) << 23;        // bits of 2^round(x)
    uint32_t sh = (xh - 0x4B3FFF81u) << 23;
    u64 sc;
    asm("mov.b64 %0, {%1, %2};" : "=l"(sc) : "r"(sl), "r"(sh));
    return mulx2(p, sc);
}

// ---------------------------------------------------------------------------
// Fused prep: z=0 Wq^T*qscale, z=1 Wkv^T, z=2 Wo^T, z=3 cast x -> fp16
// grid (64, 32, 4), block (32, 8)
// ---------------------------------------------------------------------------
__global__ void __launch_bounds__(256) conv_all(const float* __restrict__ x,
                                                __half* __restrict__ xhi,
                                                const float* __restrict__ W0,
                                                const float* __restrict__ W1,
                                                const float* __restrict__ W2,
                                                __half* __restrict__ T,
                                                float qscale)
{
    const int z  = blockIdx.z;
    const int tx = threadIdx.x, ty = threadIdx.y;

    if (z == 3) {   // cast x
        size_t idx = ((size_t)blockIdx.y * 64 + blockIdx.x) * 256 + ty * 32 + tx;
        const float4* in4 = (const float4*)x;
        uint2* out4 = (uint2*)xhi;
#pragma unroll
        for (int j = 0; j < 4; j++) {
            size_t i4 = idx * 4 + j;
            float4 v = in4[i4];
            __half2 hp0 = __floats2half2_rn(v.x, v.y);
            __half2 hp1 = __floats2half2_rn(v.z, v.w);
            uint2 hv;
            hv.x = *(uint32_t*)&hp0; hv.y = *(uint32_t*)&hp1;
            out4[i4] = hv;
        }
        return;
    }

    const float* W; __half* Thi; int N; float scale = 1.0f;
    if (z == 0)      { if (blockIdx.x >= 32) return; W = W0; Thi = T;           N = 1024; scale = qscale; }
    else if (z == 1) {                               W = W1; Thi = T + 1048576; N = 2048; }
    else             { if (blockIdx.x >= 32) return; W = W2; Thi = T + 3145728; N = 1024; }

    __shared__ float s[32][33];
    const int kt = blockIdx.y * 32, nt = blockIdx.x * 32;
#pragma unroll
    for (int r = 0; r < 4; r++) {
        int k = ty + r * 8;
        s[k][tx] = W[(size_t)(kt + k) * N + nt + tx];
    }
    __syncthreads();
#pragma unroll
    for (int r = 0; r < 4; r++) {
        int n = ty + r * 8;
        Thi[(size_t)(nt + n) * 1024 + kt + tx] = __float2half_rn(s[tx][n] * scale);
    }
}

// ---------------------------------------------------------------------------
// HMMA fp16 GEMM (1-term):  C = Ahi @ Bhi^T   (B pre-transposed [N][K=1024])
// Tile 128x128, K-chunk 64, 256 thr, warp tile 32x64, double-buffered cp.async.
// Output: fp32 (+bias) if C, else fp16.
// ---------------------------------------------------------------------------
#define TILE_B    18432          // 128 rows * 144 B
#define GEMM_SMEM (2 * 2 * TILE_B)   // 73728

__global__ void __launch_bounds__(256) gemm_hmma(const __half* __restrict__ Ahi,
                                                 const __half* __restrict__ Bhi,
                                                 float* __restrict__ C,
                                                 __half* __restrict__ Chi,
                                                 int N,
                                                 const float* __restrict__ bias)
{
    extern __shared__ char smem[];
    const uint32_t sbase = smem_u32(smem);
    const int t    = threadIdx.x;
    const int lane = t & 31;
    const int wid  = t >> 5;
    const int bm   = blockIdx.y * 128;
    const int bn   = blockIdx.x * 128;
    const int wm   = (wid >> 1) * 32;
    const int wn   = (wid & 1) * 64;

    const uint32_t a_off = (uint32_t)(wm + (lane & 15)) * 144 + (uint32_t)(lane >> 4) * 16;
    const uint32_t b_off = (uint32_t)(wn + ((lane >> 4) & 1) * 8 + (lane & 7)) * 144
                         + (uint32_t)((lane >> 3) & 1) * 16;

    const __half* srcs[2] = { Ahi + (size_t)bm * 1024, Bhi + (size_t)bn * 1024 };

    auto issue = [&](int it) {
        const uint32_t bufb = sbase + (it & 1) * (2 * TILE_B);
        const int k0 = it * 64;
#pragma unroll
        for (int r = 0; r < 2; r++) {
            const __half* gb = srcs[r] + k0;
            const uint32_t sb = bufb + r * TILE_B;
#pragma unroll
            for (int i = 0; i < 4; i++) {
                int c   = i * 256 + t;
                int row = c >> 3;
                int col = c & 7;
                CP_ASYNC16(sb + row * 144 + col * 16,
                           gb + (size_t)row * 1024 + col * 8);
            }
        }
        CP_COMMIT();
    };

    float c[2][8][4];
#pragma unroll
    for (int mi = 0; mi < 2; mi++)
#pragma unroll
        for (int nj = 0; nj < 8; nj++)
#pragma unroll
            for (int k = 0; k < 4; k++) c[mi][nj][k] = 0.f;

    issue(0);
    issue(1);

    const int NITER = 16;
    for (int it = 0; it < NITER; it++) {
        if (it + 1 < NITER) { CP_WAIT1(); } else { CP_WAIT0(); }
        __syncthreads();

        const uint32_t bufb = sbase + (it & 1) * (2 * TILE_B);
        const uint32_t Ah = bufb, Bh = bufb + TILE_B;

#pragma unroll
        for (int ks = 0; ks < 4; ks++) {
            const uint32_t ko = ks * 32;
            uint32_t ah0[4], ah1[4];
            ldsm4(ah0, Ah + a_off + ko);
            ldsm4(ah1, Ah + a_off + 16 * 144 + ko);
            uint32_t bh[4][4];
#pragma unroll
            for (int jj = 0; jj < 4; jj++)
                ldsm4(bh[jj], Bh + b_off + jj * 16 * 144 + ko);
#pragma unroll
            for (int nj = 0; nj < 8; nj++) {
                const uint32_t b0 = bh[nj >> 1][(nj & 1) * 2], b1 = bh[nj >> 1][(nj & 1) * 2 + 1];
                mma16816(c[0][nj], ah0, b0, b1);
                mma16816(c[1][nj], ah1, b0, b1);
            }
        }
        __syncthreads();
        if (it + 2 < NITER) issue(it + 2);
    }

    const int g = lane >> 2, tg = lane & 3;
#pragma unroll
    for (int mi = 0; mi < 2; mi++) {
#pragma unroll
        for (int nj = 0; nj < 8; nj++) {
            int row = bm + wm + 16 * mi + g;
            int col = bn + wn + 8 * nj + 2 * tg;
            if (Chi) {
                *(uint32_t*)(Chi + (size_t)row * N + col)       = pf16(c[mi][nj][0], c[mi][nj][1]);
                *(uint32_t*)(Chi + (size_t)(row + 8) * N + col) = pf16(c[mi][nj][2], c[mi][nj][3]);
            } else {
                float b0 = 0.f, b1 = 0.f;
                if (bias) { b0 = bias[col]; b1 = bias[col + 1]; }
                float2 v0 = make_float2(c[mi][nj][0] + b0, c[mi][nj][1] + b1);
                float2 v1 = make_float2(c[mi][nj][2] + b0, c[mi][nj][3] + b1);
                *(float2*)(C + (size_t)row * N + col)       = v0;
                *(float2*)(C + (size_t)(row + 8) * N + col) = v1;
            }
        }
    }
}

// ---------------------------------------------------------------------------
// HMMA causal flash attention, unnormalized exp2 softmax, packed-f32x2 exp.
// 128-key kv buffers processed in two 64-key halves; exp interleaved with PV;
// fully-masked warp tiles skipped. smem 73728 B (2 CTAs/SM).
// ---------------------------------------------------------------------------
#define KT2_B   18432           // 128 rows * 144 B
#define ABUF_B  (2 * KT2_B)     // K | V  = 36864
#define ATTN_SMEM (2 * ABUF_B)  // 73728
#define QKV_LD 3072

__global__ void __launch_bounds__(256) attn_mma(const __half* __restrict__ QKV,
                                                __half* __restrict__ Ohi)
{
    extern __shared__ char smem[];
    const uint32_t sbase = smem_u32(smem);
    const int t    = threadIdx.x;
    const int lane = t & 31;
    const int wid  = t >> 5;
    const int g    = lane >> 2;
    const int tg   = lane & 3;

    const int qt = 15 - (int)blockIdx.x;     // heavy tiles first
    const int h  = blockIdx.y;
    const int b  = blockIdx.z;
    const int qb = qt * 128;
    const int wm = wid * 16;

    // -------- stage Q tile (128 x 64) into smem, load A frags --------
    {
        const __half* qh_g = QKV + ((size_t)(b * 2048 + qb)) * QKV_LD + h * 64;
#pragma unroll
        for (int i = 0; i < 4; i++) {
            int idx = i * 256 + t;           // 0..1023
            int row = idx >> 3, cc = idx & 7;
            CP_ASYNC16(sbase + row * 144 + cc * 16, qh_g + (size_t)row * QKV_LD + cc * 8);
        }
        CP_COMMIT();
        CP_WAIT0();
        __syncthreads();
    }
    uint32_t qh[4][4];
    {
        const uint32_t a_base = (uint32_t)(wm + (lane & 15)) * 144 + (uint32_t)(lane >> 4) * 16;
#pragma unroll
        for (int ks = 0; ks < 4; ks++)
            ldsm4(qh[ks], sbase + a_base + ks * 32);
    }
    __syncthreads();   // Q frags in regs before buffers get overwritten

    // -------- kv pipeline: 128-key tiles --------
    const __half* kv_base = QKV + ((size_t)(b * 2048)) * QKV_LD + h * 64;
    const int ntk2 = qt + 1;                 // number of 128-key tiles

    auto issue = [&](int kt2) {
        const uint32_t bufb = sbase + (kt2 & 1) * ABUF_B;
        const size_t rbase = (size_t)(kt2 * 128) * QKV_LD;
        const __half* srcs[2] = { kv_base + rbase + 1024, kv_base + rbase + 2048 }; // K | V
#pragma unroll
        for (int r = 0; r < 2; r++) {
#pragma unroll
            for (int i = 0; i < 4; i++) {
                int idx = i * 256 + t;       // 0..1023 (128 rows x 8 chunks)
                int row = idx >> 3, cc = idx & 7;
                CP_ASYNC16(bufb + r * KT2_B + row * 144 + cc * 16,
                           srcs[r] + (size_t)row * QKV_LD + cc * 8);
            }
        }
        CP_COMMIT();
    };

    issue(0);
    if (ntk2 > 1) issue(1);

    u64 lacc0 = pk64(0.f, 0.f), lacc1 = pk64(0.f, 0.f);   // packed partial row sums
    float o[8][4];
#pragma unroll
    for (int nj = 0; nj < 8; nj++)
#pragma unroll
        for (int k = 0; k < 4; k++) o[nj][k] = 0.f;

    const uint32_t b_off = (uint32_t)(((lane >> 4) & 1) * 8 + (lane & 7)) * 144
                         + (uint32_t)((lane >> 3) & 1) * 16;
    const uint32_t v_off = (uint32_t)((lane & 7) + ((lane >> 3) & 1) * 8) * 144
                         + (uint32_t)(lane >> 4) * 16;

    for (int kt2 = 0; kt2 < ntk2; kt2++) {
        if (kt2 + 1 < ntk2) { CP_WAIT1(); } else { CP_WAIT0(); }
        __syncthreads();

        const uint32_t bufb = sbase + (kt2 & 1) * ABUF_B;

#pragma unroll
        for (int hh = 0; hh < 2; hh++) {
            const int kb = kt2 * 128 + hh * 64;
            if (kb > qb + wm + 15) break;    // fully-masked warp tile

            const uint32_t Kh = bufb + hh * 9216;
            const uint32_t Vh = bufb + KT2_B + hh * 9216;

            // ---- S = Q K^T ----
            float s[8][4];
#pragma unroll
            for (int nj = 0; nj < 8; nj++)
#pragma unroll
                for (int k = 0; k < 4; k++) s[nj][k] = 0.f;

#pragma unroll
            for (int ks = 0; ks < 4; ks++) {
                const uint32_t ko = ks * 32;
#pragma unroll
                for (int nj2 = 0; nj2 < 4; nj2++) {
                    uint32_t kh[4];
                    ldsm4(kh, Kh + b_off + nj2 * 16 * 144 + ko);
                    mma16816(s[2 * nj2],     qh[ks], kh[0], kh[1]);
                    mma16816(s[2 * nj2 + 1], qh[ks], kh[2], kh[3]);
                }
            }

            // ---- causal mask: -30 ----
            const int row0 = qb + wm + g, row1 = row0 + 8;
            if (kb + 63 > qb + wm) {
#pragma unroll
                for (int nj = 0; nj < 8; nj++) {
                    int col = kb + 8 * nj + 2 * tg;
                    if (col     > row0) s[nj][0] = -30.f;
                    if (col + 1 > row0) s[nj][1] = -30.f;
                    if (col     > row1) s[nj][2] = -30.f;
                    if (col + 1 > row1) s[nj][3] = -30.f;
                }
            }

            // ---- interleaved exp + PV ----
#pragma unroll
            for (int ks = 0; ks < 4; ks++) {
                u64 p01a = exp2x2(pk64(s[2 * ks][0],     s[2 * ks][1]));
                u64 p23a = exp2x2(pk64(s[2 * ks][2],     s[2 * ks][3]));
                u64 p01b = exp2x2(pk64(s[2 * ks + 1][0], s[2 * ks + 1][1]));
                u64 p23b = exp2x2(pk64(s[2 * ks + 1][2], s[2 * ks + 1][3]));
                lacc0 = addx2(lacc0, addx2(p01a, p01b));
                lacc1 = addx2(lacc1, addx2(p23a, p23b));
                uint32_t phi[4];
                float fa, fb;
                upk64(p01a, fa, fb); phi[0] = pf16(fa, fb);
                upk64(p23a, fa, fb); phi[1] = pf16(fa, fb);
                upk64(p01b, fa, fb); phi[2] = pf16(fa, fb);
                upk64(p23b, fa, fb); phi[3] = pf16(fa, fb);

                const uint32_t kro = ks * 16 * 144;
#pragma unroll
                for (int dc = 0; dc < 4; dc++) {
                    uint32_t vh[4];
                    ldsm4t(vh, Vh + v_off + kro + dc * 32);
                    mma16816(o[2 * dc],     phi, vh[0], vh[1]);
                    mma16816(o[2 * dc + 1], phi, vh[2], vh[3]);
                }
            }
        }

        __syncthreads();
        if (kt2 + 2 < ntk2) issue(kt2 + 2);
    }

    // ---- final row-sum reduction, epilogue ----
    float la, lb, l0, l1;
    upk64(lacc0, la, lb); l0 = la + lb;
    upk64(lacc1, la, lb); l1 = la + lb;
    l0 += __shfl_xor_sync(0xffffffffu, l0, 1);
    l0 += __shfl_xor_sync(0xffffffffu, l0, 2);
    l1 += __shfl_xor_sync(0xffffffffu, l1, 1);
    l1 += __shfl_xor_sync(0xffffffffu, l1, 2);
    const float inv0 = 1.0f / l0, inv1 = 1.0f / l1;
    const int row0 = b * 2048 + qb + wm + g;
#pragma unroll
    for (int nj = 0; nj < 8; nj++) {
        int col = h * 64 + 8 * nj + 2 * tg;
        *(uint32_t*)(Ohi + (size_t)row0 * 1024 + col)       = pf16(o[nj][0] * inv0, o[nj][1] * inv0);
        *(uint32_t*)(Ohi + (size_t)(row0 + 8) * 1024 + col) = pf16(o[nj][2] * inv1, o[nj][3] * inv1);
    }
}

// ---------------------------------------------------------------------------
// Launch
// ---------------------------------------------------------------------------
extern "C" void kernel_launch(void* const* d_in, const int* in_sizes, int n_in,
                              void* d_out, int out_size)
{
    (void)in_sizes; (void)n_in; (void)out_size;
    const float* x   = (const float*)d_in[0];
    const float* Wq  = (const float*)d_in[1];
    const float* Wkv = (const float*)d_in[2];
    const float* Wo  = (const float*)d_in[3];
    const float* bo  = (const float*)d_in[4];
    float* out = (float*)d_out;

    __half *xhi, *wthi, *qkv, *ohi;
    cudaGetSymbolAddress((void**)&xhi,  g_xhi);
    cudaGetSymbolAddress((void**)&wthi, g_wthi);
    cudaGetSymbolAddress((void**)&qkv,  g_qkv);
    cudaGetSymbolAddress((void**)&ohi,  g_ohi);

    cudaFuncSetAttribute(gemm_hmma, cudaFuncAttributeMaxDynamicSharedMemorySize, GEMM_SMEM);
    cudaFuncSetAttribute(attn_mma,  cudaFuncAttributeMaxDynamicSharedMemorySize, ATTN_SMEM);

    __half *wo_hi = wthi + 3145728;
    const float qscale = 0.125f * 1.4426950408889634f;   // D^-0.5 * log2(e)

    // fused prep: weight transposes + x cast in one launch
    conv_all<<<dim3(64, 32, 4), dim3(32, 8)>>>(x, xhi, Wq, Wkv, Wo, wthi, qscale);

    // fused qkv = x @ [Wq*qscale | Wkv]  -> fp16 [8192, 3072]
    gemm_hmma<<<dim3(24, 64), 256, GEMM_SMEM>>>(xhi, wthi, nullptr, qkv, 3072, nullptr);
    // attention -> fp16
    attn_mma<<<dim3(16, 16, 4), 256, ATTN_SMEM>>>(qkv, ohi);
    // out = o @ Wo + bo -> fp32
    gemm_hmma<<<dim3(8, 64), 256, GEMM_SMEM>>>(ohi, wo_hi, out, nullptr, 1024, bo);
}